// round 4
// baseline (speedup 1.0000x reference)
#include <cuda_runtime.h>
#include <cuda_bf16.h>
#include <cstdint>
#include <cstddef>

// R2Ntab: B=131072, F=256, R=128, O=1
#define F_DIM 256
#define R_DIM 128
#define TILE_M 128
#define GRID_CTAS 148

// ---------------- device scratch (no allocs allowed) ----------------
__device__ __align__(16) float         g_wexact[R_DIM * F_DIM]; // exact masked weights fp32
__device__ __align__(16) __nv_bfloat16 g_wb[R_DIM * F_DIM];     // bf16 masked weights [r][f]
__device__ float g_thresh[R_DIM];  // dot > thresh  <=> rule fires (inf if OR-gate off)
__device__ float g_bound[R_DIM];   // guaranteed |bf16dot - exactdot| bound per rule

// ---------------- helpers ----------------
static __device__ __forceinline__ uint32_t smem_u32(const void* p) {
    uint32_t a;
    asm("{ .reg .u64 t; cvta.to.shared.u64 t, %1; cvt.u32.u64 %0, t; }" : "=r"(a) : "l"(p));
    return a;
}

static __device__ __forceinline__ void ldmatrix_x4(uint32_t& r0, uint32_t& r1,
                                                   uint32_t& r2, uint32_t& r3,
                                                   uint32_t addr) {
    asm volatile("ldmatrix.sync.aligned.m8n8.x4.shared.b16 {%0,%1,%2,%3}, [%4];"
                 : "=r"(r0), "=r"(r1), "=r"(r2), "=r"(r3) : "r"(addr));
}

static __device__ __forceinline__ void mma_bf16(float* c, uint32_t a0, uint32_t a1,
                                                uint32_t a2, uint32_t a3,
                                                uint32_t b0, uint32_t b1) {
    asm volatile(
        "mma.sync.aligned.m16n8k16.row.col.f32.bf16.bf16.f32 "
        "{%0,%1,%2,%3}, {%4,%5,%6,%7}, {%8,%9}, {%0,%1,%2,%3};"
        : "+f"(c[0]), "+f"(c[1]), "+f"(c[2]), "+f"(c[3])
        : "r"(a0), "r"(a1), "r"(a2), "r"(a3), "r"(b0), "r"(b1));
}

// ---------------- SMEM layout ----------------
// A tiles (bf16, swizzled): row stride 512B, 16B unit u' = u ^ (row&7)
static constexpr int A0_OFF   = 0;
static constexpr int A_BYTES  = TILE_M * F_DIM * 2;    // 65536
static constexpr int A1_OFF   = A0_OFF + A_BYTES;      // 65536
static constexpr int B_OFF    = A1_OFF + A_BYTES;      // 131072
static constexpr int B_BYTES  = R_DIM * F_DIM * 2;     // 65536
static constexpr int PART_OFF = B_OFF + B_BYTES;       // 196608  (2 parities x 128 rows x 4 ints)
static constexpr int SMEM_TOTAL = PART_OFF + 2 * TILE_M * 4 * 4;  // 200704

// ---------------- precompute: mask, bf16 weights, thresholds, error bounds ----------------
__global__ void r2ntab_prep(const float* __restrict__ w_cancel,
                            const float* __restrict__ w_and,
                            const float* __restrict__ b_and,
                            const float* __restrict__ w_or) {
    int r = threadIdx.x;
    if (r >= R_DIM) return;
    float relu_sum = 0.0f, abs_sum = 0.0f;
    for (int f = 0; f < F_DIM; f++) {
        float w = (w_cancel[f] < 0.0f) ? 0.0f : w_and[r * F_DIM + f];
        g_wexact[r * F_DIM + f] = w;
        g_wb[r * F_DIM + f] = __float2bfloat16(w);
        relu_sum += fmaxf(w, 0.0f);
        abs_sum  += fabsf(w);
    }
    // rule fires <=> dot > 0.999999 - b_and + relu_sum ; OR gate via w_or sign
    if (w_or[r] > 0.0f) {
        g_thresh[r] = 0.999999f - b_and[r] + relu_sum;
        g_bound[r]  = abs_sum * 0.00390625f + 5e-4f;   // 2^-8 rel bf16 rounding + fp32 accum slack
    } else {
        g_thresh[r] = __int_as_float(0x7f800000);      // +inf: never fires
        g_bound[r]  = 0.0f;                            // never flagged
    }
}

// ---------------- tile loader: gmem fp32 -> bf16 swizzled smem ----------------
static __device__ __forceinline__ void load_tile(const float* __restrict__ x,
                                                 int tile, char* __restrict__ abase,
                                                 int tid) {
    const float4* xp = reinterpret_cast<const float4*>(x) + (size_t)tile * TILE_M * (F_DIM / 4);
    #pragma unroll 8
    for (int i = tid; i < TILE_M * (F_DIM / 4); i += 256) {
        int row = i >> 6;          // 0..127
        int q   = i & 63;          // float4 index in row (f0 = 4q)
        float4 v = xp[i];
        __nv_bfloat162 p0 = __floats2bfloat162_rn(v.x, v.y);
        __nv_bfloat162 p1 = __floats2bfloat162_rn(v.z, v.w);
        uint32_t u    = (uint32_t)(q >> 1);                 // 16B unit = f0/8
        uint32_t off  = (uint32_t)row * 512u + ((u ^ (row & 7)) << 4) + ((q & 1) << 3);
        uint2 val;
        val.x = *reinterpret_cast<uint32_t*>(&p0);
        val.y = *reinterpret_cast<uint32_t*>(&p1);
        *reinterpret_cast<uint2*>(abase + off) = val;
    }
}

// exact fp32 recheck for near-threshold elements (guaranteed-correct slow path, ~0 hits/run)
static __device__ __noinline__ int exact_check(const float* __restrict__ x,
                                               int g_row, int rule) {
    const float4* xr = reinterpret_cast<const float4*>(x + (size_t)g_row * F_DIM);
    const float4* wr = reinterpret_cast<const float4*>(g_wexact + rule * F_DIM);
    float s = 0.0f;
    #pragma unroll 8
    for (int i = 0; i < F_DIM / 4; i++) {
        float4 a = xr[i], b = wr[i];
        s += a.x * b.x + a.y * b.y + a.z * b.z + a.w * b.w;
    }
    return s > g_thresh[rule] ? 1 : 0;
}

// ---------------- main persistent kernel ----------------
__global__ void __launch_bounds__(256, 1)
r2ntab_main(const float* __restrict__ x, const float* __restrict__ b_or,
            float* __restrict__ out, int num_tiles) {
    extern __shared__ char smem[];
    const uint32_t sbase = smem_u32(smem);
    const int tid  = threadIdx.x;
    const int lane = tid & 31;
    const int wid  = tid >> 5;
    const int wm   = wid >> 2;    // 0..1 : M group (64 rows)
    const int wn   = wid & 3;     // 0..3 : N group (32 rules)

    // ---- stage B (rules) into swizzled smem, once ----
    {
        const uint4* wb4 = reinterpret_cast<const uint4*>(g_wb);
        #pragma unroll 4
        for (int i = tid; i < R_DIM * (F_DIM / 8); i += 256) {  // 16B units
            int r = i >> 5;          // rule row (32 units/row)
            int u = i & 31;          // 16B unit
            uint4 v = wb4[i];
            uint32_t off = (uint32_t)r * 512u + (((uint32_t)u ^ (r & 7)) << 4);
            *reinterpret_cast<uint4*>(smem + B_OFF + off) = v;
        }
    }

    // ---- per-thread thresholds/bounds for its 8 accumulator columns ----
    float th[8], bnd[8];
    int rule_base = wn * 32 + (lane & 3) * 2;
    #pragma unroll
    for (int nt = 0; nt < 4; nt++) {
        #pragma unroll
        for (int c = 0; c < 2; c++) {
            int rule = rule_base + nt * 8 + c;
            th[nt * 2 + c]  = g_thresh[rule];
            bnd[nt * 2 + c] = g_bound[rule];
        }
    }
    const float bor0 = b_or[0];

    // ---- ldmatrix lane-address precompute ----
    const int idx = lane >> 3;       // 0..3 (8-lane group)
    const int s3  = lane & 7;        // swizzle key (== row&7 for all our rows)
    uint32_t a_row[4];               // A row byte offsets (relative to A buffer)
    #pragma unroll
    for (int mt = 0; mt < 4; mt++)
        a_row[mt] = (uint32_t)(wm * 64 + mt * 16 + (idx & 1) * 8 + s3) * 512u;
    const uint32_t a_usel = (uint32_t)(idx >> 1);   // 0/1: k-half
    uint32_t b_row[4];               // B row absolute smem addresses (per n-tile)
    #pragma unroll
    for (int nt = 0; nt < 4; nt++)
        b_row[nt] = sbase + B_OFF + (uint32_t)(wn * 32 + nt * 8 + s3) * 512u;
    const uint32_t b_usel = (uint32_t)(idx & 1);

    int* part = reinterpret_cast<int*>(smem + PART_OFF);   // [2][128][4]

    const int t0 = blockIdx.x;
    int cur = 0;
    if (t0 < num_tiles) load_tile(x, t0, smem + A0_OFF, tid);
    __syncthreads();

    int it = 0;
    for (int t = t0; t < num_tiles; t += GRID_CTAS, it++) {
        // prefetch next tile into the other buffer (LDG overlaps; STS done before barrier)
        int tn = t + GRID_CTAS;
        if (tn < num_tiles)
            load_tile(x, tn, smem + (cur ? A0_OFF : A1_OFF), tid);

        // ---- mma: 128x128x256, warp tile 64x32 ----
        const uint32_t abuf = sbase + (cur ? A1_OFF : A0_OFF);
        float acc[4][4][4];
        #pragma unroll
        for (int mt = 0; mt < 4; mt++)
            #pragma unroll
            for (int nt = 0; nt < 4; nt++)
                #pragma unroll
                for (int c = 0; c < 4; c++) acc[mt][nt][c] = 0.0f;

        #pragma unroll 4
        for (int kt = 0; kt < 16; kt++) {
            uint32_t b[4][2];
            #pragma unroll
            for (int p = 0; p < 2; p++) {
                uint32_t u = 2 * kt + b_usel;
                uint32_t addr = b_row[2 * p + (idx >> 1)] + ((u ^ s3) << 4);
                ldmatrix_x4(b[2 * p][0], b[2 * p][1], b[2 * p + 1][0], b[2 * p + 1][1], addr);
            }
            #pragma unroll
            for (int mt = 0; mt < 4; mt++) {
                uint32_t u = 2 * kt + a_usel;
                uint32_t addr = abuf + a_row[mt] + ((u ^ s3) << 4);
                uint32_t a0, a1, a2, a3;
                ldmatrix_x4(a0, a1, a2, a3, addr);
                #pragma unroll
                for (int nt = 0; nt < 4; nt++)
                    mma_bf16(acc[mt][nt], a0, a1, a2, a3, b[nt][0], b[nt][1]);
            }
        }

        // ---- epilogue: threshold-count with exact-recheck guard ----
        const int par = it & 1;
        #pragma unroll
        for (int mt = 0; mt < 4; mt++) {
            int rA = wm * 64 + mt * 16 + (lane >> 2);   // local row (c0,c1)
            int rB = rA + 8;                            // local row (c2,c3)
            int cA = 0, cB = 0;
            #pragma unroll
            for (int nt = 0; nt < 4; nt++) {
                #pragma unroll
                for (int c = 0; c < 2; c++) {
                    int j = nt * 2 + c;
                    float vA = acc[mt][nt][c];
                    float vB = acc[mt][nt][c + 2];
                    float dA = vA - th[j];
                    float dB = vB - th[j];
                    if (fabsf(dA) <= bnd[j])
                        cA += exact_check(x, t * TILE_M + rA, rule_base + nt * 8 + c);
                    else
                        cA += (dA > 0.0f) ? 1 : 0;
                    if (fabsf(dB) <= bnd[j])
                        cB += exact_check(x, t * TILE_M + rB, rule_base + nt * 8 + c);
                    else
                        cB += (dB > 0.0f) ? 1 : 0;
                }
            }
            // quad reduce (lanes sharing the same row)
            cA += __shfl_xor_sync(0xffffffffu, cA, 1);
            cA += __shfl_xor_sync(0xffffffffu, cA, 2);
            cB += __shfl_xor_sync(0xffffffffu, cB, 1);
            cB += __shfl_xor_sync(0xffffffffu, cB, 2);
            if ((lane & 3) == 0) {
                part[par * 512 + rA * 4 + wn] = cA;
                part[par * 512 + rB * 4 + wn] = cB;
            }
        }
        __syncthreads();   // partials ready; next-tile STS complete

        if (tid < TILE_M) {
            int4 q = *reinterpret_cast<int4*>(&part[par * 512 + tid * 4]);
            out[t * TILE_M + tid] = (float)(q.x + q.y + q.z + q.w) + bor0;
        }
        cur ^= 1;
        // parity ping-pong on `part` makes a second barrier unnecessary:
        // this parity is not rewritten until 2 barriers from now.
    }
}

extern "C" void kernel_launch(void* const* d_in, const int* in_sizes, int n_in,
                              void* d_out, int out_size) {
    const float* x        = (const float*)d_in[0];
    const float* w_cancel = (const float*)d_in[1];
    const float* w_and    = (const float*)d_in[2];
    const float* b_and    = (const float*)d_in[3];
    const float* w_or     = (const float*)d_in[4];
    const float* b_or     = (const float*)d_in[5];
    float* out = (float*)d_out;

    const int B_total   = in_sizes[0] / F_DIM;   // 131072
    const int num_tiles = B_total / TILE_M;      // 1024

    cudaFuncSetAttribute(r2ntab_main, cudaFuncAttributeMaxDynamicSharedMemorySize, SMEM_TOTAL);

    r2ntab_prep<<<1, R_DIM>>>(w_cancel, w_and, b_and, w_or);
    r2ntab_main<<<GRID_CTAS, 256, SMEM_TOTAL>>>(x, b_or, out, num_tiles);
    (void)n_in; (void)out_size;
}

// round 5
// speedup vs baseline: 2.3224x; 2.3224x over previous
#include <cuda_runtime.h>
#include <cuda_bf16.h>
#include <cstdint>
#include <cstddef>

// R2Ntab: B=131072, F=256, R=128, O=1
#define F_DIM 256
#define R_DIM 128
#define TILE_M 128
#define GRID_CTAS 148

// ---------------- device scratch (no allocs allowed) ----------------
__device__ __align__(16) float         g_wexact[R_DIM * F_DIM]; // exact masked weights fp32
__device__ __align__(16) __nv_bfloat16 g_wb[R_DIM * F_DIM];     // bf16 masked weights [r][f]
__device__ float g_thresh[R_DIM];  // dot > thresh  <=> rule fires (inf if OR-gate off)
__device__ float g_bound[R_DIM];   // guaranteed |bf16dot - exactdot| bound per rule

// ---------------- helpers ----------------
static __device__ __forceinline__ uint32_t smem_u32(const void* p) {
    uint32_t a;
    asm("{ .reg .u64 t; cvta.to.shared.u64 t, %1; cvt.u32.u64 %0, t; }" : "=r"(a) : "l"(p));
    return a;
}

static __device__ __forceinline__ void ldmatrix_x4(uint32_t& r0, uint32_t& r1,
                                                   uint32_t& r2, uint32_t& r3,
                                                   uint32_t addr) {
    asm volatile("ldmatrix.sync.aligned.m8n8.x4.shared.b16 {%0,%1,%2,%3}, [%4];"
                 : "=r"(r0), "=r"(r1), "=r"(r2), "=r"(r3) : "r"(addr));
}

static __device__ __forceinline__ void mma_bf16(float* c, uint32_t a0, uint32_t a1,
                                                uint32_t a2, uint32_t a3,
                                                uint32_t b0, uint32_t b1) {
    asm volatile(
        "mma.sync.aligned.m16n8k16.row.col.f32.bf16.bf16.f32 "
        "{%0,%1,%2,%3}, {%4,%5,%6,%7}, {%8,%9}, {%0,%1,%2,%3};"
        : "+f"(c[0]), "+f"(c[1]), "+f"(c[2]), "+f"(c[3])
        : "r"(a0), "r"(a1), "r"(a2), "r"(a3), "r"(b0), "r"(b1));
}

// ---------------- SMEM layout ----------------
// A tiles (bf16, swizzled): row stride 512B, 16B unit u' = u ^ (row&7)
static constexpr int A0_OFF   = 0;
static constexpr int A_BYTES  = TILE_M * F_DIM * 2;    // 65536
static constexpr int A1_OFF   = A0_OFF + A_BYTES;      // 65536
static constexpr int B_OFF    = A1_OFF + A_BYTES;      // 131072
static constexpr int B_BYTES  = R_DIM * F_DIM * 2;     // 65536
static constexpr int PART_OFF = B_OFF + B_BYTES;       // 196608  (2 parities x 128 rows x 4 ints)
static constexpr int SMEM_TOTAL = PART_OFF + 2 * TILE_M * 4 * 4;  // 200704

// ---------------- precompute (parallel): mask, bf16 weights, thresholds, bounds ----
// grid = R_DIM CTAs (one rule each), 128 threads
__global__ void r2ntab_prep(const float* __restrict__ w_cancel,
                            const float* __restrict__ w_and,
                            const float* __restrict__ b_and,
                            const float* __restrict__ w_or) {
    __shared__ float s_relu[4], s_abs[4];
    const int r = blockIdx.x;
    const int t = threadIdx.x;          // 0..127
    float relu = 0.0f, absr = 0.0f;
    #pragma unroll
    for (int k = 0; k < 2; k++) {
        int f = t + 128 * k;
        float w = (w_cancel[f] < 0.0f) ? 0.0f : w_and[r * F_DIM + f];
        g_wexact[r * F_DIM + f] = w;
        g_wb[r * F_DIM + f] = __float2bfloat16(w);
        relu += fmaxf(w, 0.0f);
        absr += fabsf(w);
    }
    #pragma unroll
    for (int s = 16; s > 0; s >>= 1) {
        relu += __shfl_xor_sync(0xffffffffu, relu, s);
        absr += __shfl_xor_sync(0xffffffffu, absr, s);
    }
    if ((t & 31) == 0) { s_relu[t >> 5] = relu; s_abs[t >> 5] = absr; }
    __syncthreads();
    if (t == 0) {
        float rs = s_relu[0] + s_relu[1] + s_relu[2] + s_relu[3];
        float as = s_abs[0] + s_abs[1] + s_abs[2] + s_abs[3];
        if (w_or[r] > 0.0f) {
            g_thresh[r] = 0.999999f - b_and[r] + rs;
            g_bound[r]  = as * 0.00390625f + 5e-4f;  // 2^-8 bf16 rounding + fp32 accum slack
        } else {
            g_thresh[r] = __int_as_float(0x7f800000); // +inf: never fires
            g_bound[r]  = 0.0f;
        }
    }
}

// ---------------- tile loader (used only for the very first tile) ----------------
static __device__ __forceinline__ void load_tile(const float* __restrict__ x,
                                                 int tile, char* __restrict__ abase,
                                                 int tid) {
    const float4* xp = reinterpret_cast<const float4*>(x) + (size_t)tile * TILE_M * (F_DIM / 4);
    #pragma unroll 8
    for (int i = tid; i < TILE_M * (F_DIM / 4); i += 256) {
        int row = i >> 6;
        int q   = i & 63;
        float4 v = xp[i];
        __nv_bfloat162 p0 = __floats2bfloat162_rn(v.x, v.y);
        __nv_bfloat162 p1 = __floats2bfloat162_rn(v.z, v.w);
        uint32_t u    = (uint32_t)(q >> 1);
        uint32_t off  = (uint32_t)row * 512u + ((u ^ (row & 7)) << 4) + ((q & 1) << 3);
        uint2 val;
        val.x = *reinterpret_cast<uint32_t*>(&p0);
        val.y = *reinterpret_cast<uint32_t*>(&p1);
        *reinterpret_cast<uint2*>(abase + off) = val;
    }
}

// exact fp32 recheck for near-threshold elements (guaranteed-correct slow path)
static __device__ __noinline__ int exact_check(const float* __restrict__ x,
                                               int g_row, int rule) {
    const float4* xr = reinterpret_cast<const float4*>(x + (size_t)g_row * F_DIM);
    const float4* wr = reinterpret_cast<const float4*>(g_wexact + rule * F_DIM);
    float s = 0.0f;
    #pragma unroll 8
    for (int i = 0; i < F_DIM / 4; i++) {
        float4 a = xr[i], b = wr[i];
        s += a.x * b.x + a.y * b.y + a.z * b.z + a.w * b.w;
    }
    return s > g_thresh[rule] ? 1 : 0;
}

// ---------------- main persistent kernel ----------------
__global__ void __launch_bounds__(256, 1)
r2ntab_main(const float* __restrict__ x, const float* __restrict__ b_or,
            float* __restrict__ out, int num_tiles) {
    extern __shared__ char smem[];
    const uint32_t sbase = smem_u32(smem);
    const int tid  = threadIdx.x;
    const int lane = tid & 31;
    const int wid  = tid >> 5;
    const int wm   = wid >> 2;    // 0..1 : M group (64 rows)
    const int wn   = wid & 3;     // 0..3 : N group (32 rules)

    // ---- stage B (rules) into swizzled smem, once ----
    {
        const uint4* wb4 = reinterpret_cast<const uint4*>(g_wb);
        #pragma unroll 4
        for (int i = tid; i < R_DIM * (F_DIM / 8); i += 256) {
            int r = i >> 5;
            int u = i & 31;
            uint4 v = wb4[i];
            uint32_t off = (uint32_t)r * 512u + (((uint32_t)u ^ (r & 7)) << 4);
            *reinterpret_cast<uint4*>(smem + B_OFF + off) = v;
        }
    }

    // ---- per-thread thresholds/bounds for its 8 accumulator columns ----
    float th[8], bnd[8];
    int rule_base = wn * 32 + (lane & 3) * 2;
    #pragma unroll
    for (int nt = 0; nt < 4; nt++)
        #pragma unroll
        for (int c = 0; c < 2; c++) {
            int rule = rule_base + nt * 8 + c;
            th[nt * 2 + c]  = g_thresh[rule];
            bnd[nt * 2 + c] = g_bound[rule];
        }
    const float bor0 = b_or[0];

    // ---- ldmatrix lane-address precompute ----
    const int idx = lane >> 3;
    const int s3  = lane & 7;
    uint32_t a_row[4];
    #pragma unroll
    for (int mt = 0; mt < 4; mt++)
        a_row[mt] = (uint32_t)(wm * 64 + mt * 16 + (idx & 1) * 8 + s3) * 512u;
    const uint32_t a_usel = (uint32_t)(idx >> 1);
    uint32_t b_row[4];
    #pragma unroll
    for (int nt = 0; nt < 4; nt++)
        b_row[nt] = sbase + B_OFF + (uint32_t)(wn * 32 + nt * 8 + s3) * 512u;
    const uint32_t b_usel = (uint32_t)(idx & 1);

    int* part = reinterpret_cast<int*>(smem + PART_OFF);   // [2][128][4]

    // per-thread invariants for the pipelined next-tile loader:
    // flat index i = tid + 256*j  ->  row = (tid>>6) + 4*j , q = tid&63 (fixed)
    const int q_l    = tid & 63;
    const int row0_l = tid >> 6;                 // 0..3
    const uint32_t u_l = (uint32_t)(q_l >> 1);
    const uint32_t halfoff_l = ((uint32_t)(q_l & 1)) << 3;

    const int t0 = blockIdx.x;
    int cur = 0;
    if (t0 < num_tiles) load_tile(x, t0, smem + A0_OFF, tid);
    __syncthreads();

    int it = 0;
    for (int t = t0; t < num_tiles; t += GRID_CTAS, it++) {
        const int tn = t + GRID_CTAS;
        const bool has_next = (tn < num_tiles);
        const float4* xn = reinterpret_cast<const float4*>(x) +
                           (size_t)tn * TILE_M * (F_DIM / 4);
        char* nbuf = smem + (cur ? A0_OFF : A1_OFF);

        // prologue: issue LDG for load-group 0 (j = 0..7)
        float4 buf[8];
        if (has_next) {
            #pragma unroll
            for (int jj = 0; jj < 8; jj++)
                buf[jj] = xn[tid + 256 * jj];
        }

        const uint32_t abuf = sbase + (cur ? A1_OFF : A0_OFF);
        float acc[4][4][4];
        #pragma unroll
        for (int mt = 0; mt < 4; mt++)
            #pragma unroll
            for (int nt = 0; nt < 4; nt++)
                #pragma unroll
                for (int c = 0; c < 4; c++) acc[mt][nt][c] = 0.0f;

        // ---- mma k-loop with interleaved next-tile STS/LDG ----
        #pragma unroll
        for (int kt = 0; kt < 16; kt++) {
            uint32_t b[4][2];
            #pragma unroll
            for (int p = 0; p < 2; p++) {
                uint32_t u = 2 * kt + b_usel;
                uint32_t addr = b_row[2 * p + (idx >> 1)] + ((u ^ s3) << 4);
                ldmatrix_x4(b[2 * p][0], b[2 * p][1], b[2 * p + 1][0], b[2 * p + 1][1], addr);
            }
            #pragma unroll
            for (int mt = 0; mt < 4; mt++) {
                uint32_t u = 2 * kt + a_usel;
                uint32_t addr = abuf + a_row[mt] + ((u ^ s3) << 4);
                uint32_t a0, a1, a2, a3;
                ldmatrix_x4(a0, a1, a2, a3, addr);
                #pragma unroll
                for (int nt = 0; nt < 4; nt++)
                    mma_bf16(acc[mt][nt], a0, a1, a2, a3, b[nt][0], b[nt][1]);
            }

            // every 4th k-step: drain the arrived load group to smem, issue next group
            if ((kt & 3) == 3 && has_next) {
                const int g = kt >> 2;           // 0..3
                #pragma unroll
                for (int jj = 0; jj < 8; jj++) {
                    const int j   = g * 8 + jj;
                    const int row = row0_l + 4 * j;
                    __nv_bfloat162 p0 = __floats2bfloat162_rn(buf[jj].x, buf[jj].y);
                    __nv_bfloat162 p1 = __floats2bfloat162_rn(buf[jj].z, buf[jj].w);
                    uint32_t off = (uint32_t)row * 512u +
                                   ((u_l ^ (uint32_t)(row & 7)) << 4) + halfoff_l;
                    uint2 val;
                    val.x = *reinterpret_cast<uint32_t*>(&p0);
                    val.y = *reinterpret_cast<uint32_t*>(&p1);
                    *reinterpret_cast<uint2*>(nbuf + off) = val;
                }
                if (g < 3) {
                    #pragma unroll
                    for (int jj = 0; jj < 8; jj++)
                        buf[jj] = xn[tid + 256 * ((g + 1) * 8 + jj)];
                }
            }
        }

        // ---- epilogue: threshold-count with exact-recheck guard ----
        const int par = it & 1;
        #pragma unroll
        for (int mt = 0; mt < 4; mt++) {
            int rA = wm * 64 + mt * 16 + (lane >> 2);
            int rB = rA + 8;
            int cA = 0, cB = 0;
            #pragma unroll
            for (int nt = 0; nt < 4; nt++) {
                #pragma unroll
                for (int c = 0; c < 2; c++) {
                    int j = nt * 2 + c;
                    float dA = acc[mt][nt][c] - th[j];
                    float dB = acc[mt][nt][c + 2] - th[j];
                    if (fabsf(dA) <= bnd[j])
                        cA += exact_check(x, t * TILE_M + rA, rule_base + nt * 8 + c);
                    else
                        cA += (dA > 0.0f) ? 1 : 0;
                    if (fabsf(dB) <= bnd[j])
                        cB += exact_check(x, t * TILE_M + rB, rule_base + nt * 8 + c);
                    else
                        cB += (dB > 0.0f) ? 1 : 0;
                }
            }
            cA += __shfl_xor_sync(0xffffffffu, cA, 1);
            cA += __shfl_xor_sync(0xffffffffu, cA, 2);
            cB += __shfl_xor_sync(0xffffffffu, cB, 1);
            cB += __shfl_xor_sync(0xffffffffu, cB, 2);
            if ((lane & 3) == 0) {
                part[par * 512 + rA * 4 + wn] = cA;
                part[par * 512 + rB * 4 + wn] = cB;
            }
        }
        __syncthreads();   // partials ready; next-tile STS complete

        if (tid < TILE_M) {
            int4 qv = *reinterpret_cast<int4*>(&part[par * 512 + tid * 4]);
            out[t * TILE_M + tid] = (float)(qv.x + qv.y + qv.z + qv.w) + bor0;
        }
        cur ^= 1;
        // parity ping-pong on `part`: this parity isn't rewritten until 2 barriers later.
    }
}

extern "C" void kernel_launch(void* const* d_in, const int* in_sizes, int n_in,
                              void* d_out, int out_size) {
    const float* x        = (const float*)d_in[0];
    const float* w_cancel = (const float*)d_in[1];
    const float* w_and    = (const float*)d_in[2];
    const float* b_and    = (const float*)d_in[3];
    const float* w_or     = (const float*)d_in[4];
    const float* b_or     = (const float*)d_in[5];
    float* out = (float*)d_out;

    const int B_total   = in_sizes[0] / F_DIM;   // 131072
    const int num_tiles = B_total / TILE_M;      // 1024

    cudaFuncSetAttribute(r2ntab_main, cudaFuncAttributeMaxDynamicSharedMemorySize, SMEM_TOTAL);

    r2ntab_prep<<<R_DIM, 128>>>(w_cancel, w_and, b_and, w_or);
    r2ntab_main<<<GRID_CTAS, 256, SMEM_TOTAL>>>(x, b_or, out, num_tiles);
    (void)n_in; (void)out_size;
}

// round 6
// speedup vs baseline: 2.5065x; 1.0793x over previous
#include <cuda_runtime.h>
#include <cuda_bf16.h>
#include <cstdint>
#include <cstddef>

// R2Ntab: B=131072, F=256, R=128, O=1
#define F_DIM 256
#define R_DIM 128
#define TILE_M 128
#define GRID_CTAS 148
#define NTHREADS 512

// ---------------- device scratch (no allocs allowed) ----------------
__device__ __align__(16) float         g_wexact[R_DIM * F_DIM]; // exact masked weights fp32
__device__ __align__(16) __nv_bfloat16 g_wb[R_DIM * F_DIM];     // bf16 masked weights [r][f]
__device__ float g_thresh[R_DIM];  // dot > thresh  <=> rule fires (inf if OR-gate off)
__device__ float g_bound[R_DIM];   // guaranteed |bf16dot - exactdot| bound per rule

// ---------------- helpers ----------------
static __device__ __forceinline__ uint32_t smem_u32(const void* p) {
    uint32_t a;
    asm("{ .reg .u64 t; cvta.to.shared.u64 t, %1; cvt.u32.u64 %0, t; }" : "=r"(a) : "l"(p));
    return a;
}

static __device__ __forceinline__ void ldmatrix_x4(uint32_t& r0, uint32_t& r1,
                                                   uint32_t& r2, uint32_t& r3,
                                                   uint32_t addr) {
    asm volatile("ldmatrix.sync.aligned.m8n8.x4.shared.b16 {%0,%1,%2,%3}, [%4];"
                 : "=r"(r0), "=r"(r1), "=r"(r2), "=r"(r3) : "r"(addr));
}

static __device__ __forceinline__ void mma_bf16(float* c, uint32_t a0, uint32_t a1,
                                                uint32_t a2, uint32_t a3,
                                                uint32_t b0, uint32_t b1) {
    asm volatile(
        "mma.sync.aligned.m16n8k16.row.col.f32.bf16.bf16.f32 "
        "{%0,%1,%2,%3}, {%4,%5,%6,%7}, {%8,%9}, {%0,%1,%2,%3};"
        : "+f"(c[0]), "+f"(c[1]), "+f"(c[2]), "+f"(c[3])
        : "r"(a0), "r"(a1), "r"(a2), "r"(a3), "r"(b0), "r"(b1));
}

// ---------------- SMEM layout ----------------
// A tiles (bf16, swizzled): row stride 512B, 16B unit u' = u ^ (row&7)
static constexpr int A0_OFF   = 0;
static constexpr int A_BYTES  = TILE_M * F_DIM * 2;    // 65536
static constexpr int A1_OFF   = A0_OFF + A_BYTES;      // 65536
static constexpr int B_OFF    = A1_OFF + A_BYTES;      // 131072
static constexpr int B_BYTES  = R_DIM * F_DIM * 2;     // 65536
static constexpr int PART_OFF = B_OFF + B_BYTES;       // 196608  (2 parities x 128 rows x 4 ints)
static constexpr int SMEM_TOTAL = PART_OFF + 2 * TILE_M * 4 * 4;  // 200704

// ---------------- precompute (parallel) ----------------
__global__ void r2ntab_prep(const float* __restrict__ w_cancel,
                            const float* __restrict__ w_and,
                            const float* __restrict__ b_and,
                            const float* __restrict__ w_or) {
    __shared__ float s_relu[4], s_abs[4];
    const int r = blockIdx.x;
    const int t = threadIdx.x;          // 0..127
    float relu = 0.0f, absr = 0.0f;
    #pragma unroll
    for (int k = 0; k < 2; k++) {
        int f = t + 128 * k;
        float w = (w_cancel[f] < 0.0f) ? 0.0f : w_and[r * F_DIM + f];
        g_wexact[r * F_DIM + f] = w;
        g_wb[r * F_DIM + f] = __float2bfloat16(w);
        relu += fmaxf(w, 0.0f);
        absr += fabsf(w);
    }
    #pragma unroll
    for (int s = 16; s > 0; s >>= 1) {
        relu += __shfl_xor_sync(0xffffffffu, relu, s);
        absr += __shfl_xor_sync(0xffffffffu, absr, s);
    }
    if ((t & 31) == 0) { s_relu[t >> 5] = relu; s_abs[t >> 5] = absr; }
    __syncthreads();
    if (t == 0) {
        float rs = s_relu[0] + s_relu[1] + s_relu[2] + s_relu[3];
        float as = s_abs[0] + s_abs[1] + s_abs[2] + s_abs[3];
        if (w_or[r] > 0.0f) {
            g_thresh[r] = 0.999999f - b_and[r] + rs;
            g_bound[r]  = as * 0.00390625f + 5e-4f;
        } else {
            g_thresh[r] = __int_as_float(0x7f800000);
            g_bound[r]  = 0.0f;
        }
    }
}

// ---------------- first-tile loader ----------------
static __device__ __forceinline__ void load_tile(const float* __restrict__ x,
                                                 int tile, char* __restrict__ abase,
                                                 int tid) {
    const float4* xp = reinterpret_cast<const float4*>(x) + (size_t)tile * TILE_M * (F_DIM / 4);
    #pragma unroll 8
    for (int i = tid; i < TILE_M * (F_DIM / 4); i += NTHREADS) {
        int row = i >> 6;
        int q   = i & 63;
        float4 v = xp[i];
        __nv_bfloat162 p0 = __floats2bfloat162_rn(v.x, v.y);
        __nv_bfloat162 p1 = __floats2bfloat162_rn(v.z, v.w);
        uint32_t u    = (uint32_t)(q >> 1);
        uint32_t off  = (uint32_t)row * 512u + ((u ^ (row & 7)) << 4) + ((q & 1) << 3);
        uint2 val;
        val.x = *reinterpret_cast<uint32_t*>(&p0);
        val.y = *reinterpret_cast<uint32_t*>(&p1);
        *reinterpret_cast<uint2*>(abase + off) = val;
    }
}

// exact fp32 recheck for near-threshold elements (guaranteed-correct slow path)
static __device__ __noinline__ int exact_check(const float* __restrict__ x,
                                               int g_row, int rule) {
    const float4* xr = reinterpret_cast<const float4*>(x + (size_t)g_row * F_DIM);
    const float4* wr = reinterpret_cast<const float4*>(g_wexact + rule * F_DIM);
    float s = 0.0f;
    #pragma unroll 8
    for (int i = 0; i < F_DIM / 4; i++) {
        float4 a = xr[i], b = wr[i];
        s += a.x * b.x + a.y * b.y + a.z * b.z + a.w * b.w;
    }
    return s > g_thresh[rule] ? 1 : 0;
}

// ---------------- main persistent kernel: 512 threads, warp tile 32x32 ----------------
__global__ void __launch_bounds__(NTHREADS, 1)
r2ntab_main(const float* __restrict__ x, const float* __restrict__ b_or,
            float* __restrict__ out, int num_tiles) {
    extern __shared__ char smem[];
    const uint32_t sbase = smem_u32(smem);
    const int tid  = threadIdx.x;
    const int lane = tid & 31;
    const int wid  = tid >> 5;     // 0..15
    const int wm   = wid >> 2;     // 0..3 : M group (32 rows)
    const int wn   = wid & 3;      // 0..3 : N group (32 rules)

    // ---- stage B (rules) into swizzled smem, once ----
    {
        const uint4* wb4 = reinterpret_cast<const uint4*>(g_wb);
        #pragma unroll 2
        for (int i = tid; i < R_DIM * (F_DIM / 8); i += NTHREADS) {
            int r = i >> 5;
            int u = i & 31;
            uint4 v = wb4[i];
            uint32_t off = (uint32_t)r * 512u + (((uint32_t)u ^ (r & 7)) << 4);
            *reinterpret_cast<uint4*>(smem + B_OFF + off) = v;
        }
    }

    // ---- per-thread thresholds/bounds (8 accumulator columns) ----
    float th[8], bnd[8];
    int rule_base = wn * 32 + (lane & 3) * 2;
    #pragma unroll
    for (int nt = 0; nt < 4; nt++)
        #pragma unroll
        for (int c = 0; c < 2; c++) {
            int rule = rule_base + nt * 8 + c;
            th[nt * 2 + c]  = g_thresh[rule];
            bnd[nt * 2 + c] = g_bound[rule];
        }
    const float bor0 = b_or[0];

    // ---- ldmatrix lane-address precompute ----
    const int idx = lane >> 3;
    const int s3  = lane & 7;
    uint32_t a_row[2];
    #pragma unroll
    for (int mt = 0; mt < 2; mt++)
        a_row[mt] = (uint32_t)(wm * 32 + mt * 16 + (idx & 1) * 8 + s3) * 512u;
    const uint32_t a_usel = (uint32_t)(idx >> 1);
    uint32_t b_row[4];
    #pragma unroll
    for (int nt = 0; nt < 4; nt++)
        b_row[nt] = sbase + B_OFF + (uint32_t)(wn * 32 + nt * 8 + s3) * 512u;
    const uint32_t b_usel = (uint32_t)(idx & 1);

    int* part = reinterpret_cast<int*>(smem + PART_OFF);   // [2][128][4]

    // pipelined loader invariants: i = tid + 512*j  ->  row = (tid>>6) + 8*j, q = tid&63
    const int q_l    = tid & 63;
    const int row0_l = tid >> 6;                 // 0..7
    const uint32_t u_l = (uint32_t)(q_l >> 1);
    const uint32_t halfoff_l = ((uint32_t)(q_l & 1)) << 3;

    const int t0 = blockIdx.x;
    int cur = 0;
    if (t0 < num_tiles) load_tile(x, t0, smem + A0_OFF, tid);
    __syncthreads();

    int it = 0;
    for (int t = t0; t < num_tiles; t += GRID_CTAS, it++) {
        const int tn = t + GRID_CTAS;
        const bool has_next = (tn < num_tiles);
        const float4* xn = reinterpret_cast<const float4*>(x) +
                           (size_t)tn * TILE_M * (F_DIM / 4);
        char* nbuf = smem + (cur ? A0_OFF : A1_OFF);

        // prologue: two load-groups in flight (j-groups of 4 float4 each)
        float4 buf[2][4];
        if (has_next) {
            #pragma unroll
            for (int jj = 0; jj < 4; jj++) buf[0][jj] = xn[tid + NTHREADS * jj];
            #pragma unroll
            for (int jj = 0; jj < 4; jj++) buf[1][jj] = xn[tid + NTHREADS * (4 + jj)];
        }

        const uint32_t abuf = sbase + (cur ? A1_OFF : A0_OFF);
        float acc[2][4][4];
        #pragma unroll
        for (int mt = 0; mt < 2; mt++)
            #pragma unroll
            for (int nt = 0; nt < 4; nt++)
                #pragma unroll
                for (int c = 0; c < 4; c++) acc[mt][nt][c] = 0.0f;

        // ---- mma k-loop with interleaved next-tile STS/LDG ----
        #pragma unroll
        for (int kt = 0; kt < 16; kt++) {
            uint32_t b[4][2];
            #pragma unroll
            for (int p = 0; p < 2; p++) {
                uint32_t u = 2 * kt + b_usel;
                uint32_t addr = b_row[2 * p + (idx >> 1)] + ((u ^ s3) << 4);
                ldmatrix_x4(b[2 * p][0], b[2 * p][1], b[2 * p + 1][0], b[2 * p + 1][1], addr);
            }
            #pragma unroll
            for (int mt = 0; mt < 2; mt++) {
                uint32_t u = 2 * kt + a_usel;
                uint32_t addr = abuf + a_row[mt] + ((u ^ s3) << 4);
                uint32_t a0, a1, a2, a3;
                ldmatrix_x4(a0, a1, a2, a3, addr);
                #pragma unroll
                for (int nt = 0; nt < 4; nt++)
                    mma_bf16(acc[mt][nt], a0, a1, a2, a3, b[nt][0], b[nt][1]);
            }

            // every 4th k-step: drain arrived group g, issue group g+2
            if ((kt & 3) == 3 && has_next) {
                const int g = kt >> 2;           // 0..3
                #pragma unroll
                for (int jj = 0; jj < 4; jj++) {
                    const int j   = g * 4 + jj;
                    const int row = row0_l + 8 * j;
                    float4 v = buf[g & 1][jj];
                    __nv_bfloat162 p0 = __floats2bfloat162_rn(v.x, v.y);
                    __nv_bfloat162 p1 = __floats2bfloat162_rn(v.z, v.w);
                    uint32_t off = (uint32_t)row * 512u +
                                   ((u_l ^ (uint32_t)(row & 7)) << 4) + halfoff_l;
                    uint2 val;
                    val.x = *reinterpret_cast<uint32_t*>(&p0);
                    val.y = *reinterpret_cast<uint32_t*>(&p1);
                    *reinterpret_cast<uint2*>(nbuf + off) = val;
                }
                if (g < 2) {
                    #pragma unroll
                    for (int jj = 0; jj < 4; jj++)
                        buf[g & 1][jj] = xn[tid + NTHREADS * ((g + 2) * 4 + jj)];
                }
            }
        }

        // ---- epilogue: threshold-count with exact-recheck guard ----
        const int par = it & 1;
        #pragma unroll
        for (int mt = 0; mt < 2; mt++) {
            int rA = wm * 32 + mt * 16 + (lane >> 2);
            int rB = rA + 8;
            int cA = 0, cB = 0;
            #pragma unroll
            for (int nt = 0; nt < 4; nt++) {
                #pragma unroll
                for (int c = 0; c < 2; c++) {
                    int j = nt * 2 + c;
                    float dA = acc[mt][nt][c] - th[j];
                    float dB = acc[mt][nt][c + 2] - th[j];
                    if (fabsf(dA) <= bnd[j])
                        cA += exact_check(x, t * TILE_M + rA, rule_base + nt * 8 + c);
                    else
                        cA += (dA > 0.0f) ? 1 : 0;
                    if (fabsf(dB) <= bnd[j])
                        cB += exact_check(x, t * TILE_M + rB, rule_base + nt * 8 + c);
                    else
                        cB += (dB > 0.0f) ? 1 : 0;
                }
            }
            cA += __shfl_xor_sync(0xffffffffu, cA, 1);
            cA += __shfl_xor_sync(0xffffffffu, cA, 2);
            cB += __shfl_xor_sync(0xffffffffu, cB, 1);
            cB += __shfl_xor_sync(0xffffffffu, cB, 2);
            if ((lane & 3) == 0) {
                part[par * 512 + rA * 4 + wn] = cA;
                part[par * 512 + rB * 4 + wn] = cB;
            }
        }
        __syncthreads();   // partials ready; next-tile STS complete

        if (tid < TILE_M) {
            int4 qv = *reinterpret_cast<int4*>(&part[par * 512 + tid * 4]);
            out[t * TILE_M + tid] = (float)(qv.x + qv.y + qv.z + qv.w) + bor0;
        }
        cur ^= 1;
        // parity ping-pong on `part`: this parity isn't rewritten until 2 barriers later.
    }
}

extern "C" void kernel_launch(void* const* d_in, const int* in_sizes, int n_in,
                              void* d_out, int out_size) {
    const float* x        = (const float*)d_in[0];
    const float* w_cancel = (const float*)d_in[1];
    const float* w_and    = (const float*)d_in[2];
    const float* b_and    = (const float*)d_in[3];
    const float* w_or     = (const float*)d_in[4];
    const float* b_or     = (const float*)d_in[5];
    float* out = (float*)d_out;

    const int B_total   = in_sizes[0] / F_DIM;   // 131072
    const int num_tiles = B_total / TILE_M;      // 1024

    cudaFuncSetAttribute(r2ntab_main, cudaFuncAttributeMaxDynamicSharedMemorySize, SMEM_TOTAL);

    r2ntab_prep<<<R_DIM, 128>>>(w_cancel, w_and, b_and, w_or);
    r2ntab_main<<<GRID_CTAS, NTHREADS, SMEM_TOTAL>>>(x, b_or, out, num_tiles);
    (void)n_in; (void)out_size;
}